// round 13
// baseline (speedup 1.0000x reference)
#include <cuda_runtime.h>
#include <cuda_fp16.h>
#include <cuda_bf16.h>

#define LRES 128
#define HRES 1024
#define NCH 8
#define LBLK (LRES / 2)     // 64 grid blocks per axis
#define HBLK (HRES / 2)     // 512 plane blocks per axis

// Channel-innermost fp16 scratch, blocked so one gather instruction's lanes
// land in the minimum number of 128B lines:
//   grid:   2x2x2 texel blocks = 8*16B = 128B = one line (128B aligned)
//   planes: 2x2  texel blocks = 4*16B = 64B; two W-adjacent blocks per line
__device__ __align__(128) __half g_grid_h[LRES * LRES * LRES * NCH];    // 32 MB
__device__ __align__(128) __half g_planes_h[3 * HRES * HRES * NCH];     // 48 MB

// bbox of xyz (order-preserving uint encoding); statically initialized,
// re-armed at the start of gather_kernel for the next replay.
__device__ unsigned g_bbox_min[3] = {0xFFFFFFFFu, 0xFFFFFFFFu, 0xFFFFFFFFu};
__device__ unsigned g_bbox_max[3] = {0u, 0u, 0u};

__device__ __forceinline__ unsigned f2u_ord(float f) {
    unsigned u = __float_as_uint(f);
    return (u & 0x80000000u) ? ~u : (u | 0x80000000u);
}
__device__ __forceinline__ float u2f_ord(unsigned u) {
    return __uint_as_float((u & 0x80000000u) ? (u ^ 0x80000000u) : ~u);
}

__device__ __forceinline__ uint4 pack8_half(float4 a, float4 b) {
    union { uint4 u; __half2 h[4]; } r;
    r.h[0] = __floats2half2_rn(a.x, a.y);
    r.h[1] = __floats2half2_rn(a.z, a.w);
    r.h[2] = __floats2half2_rn(b.x, b.y);
    r.h[3] = __floats2half2_rn(b.z, b.w);
    return r.u;
}

// Blocked texel slot (uint4 units) for grid (z,y,x).
__device__ __forceinline__ int gidx_blk(int z, int y, int x) {
    int B = ((z >> 1) * LBLK + (y >> 1)) * LBLK + (x >> 1);
    return B * 8 + ((z & 1) << 2) + ((y & 1) << 1) + (x & 1);
}
// Blocked texel slot for plane p, (h,w).
__device__ __forceinline__ int pidx_blk(int p, int h, int w) {
    int B = (h >> 1) * HBLK + (w >> 1);
    return p * (HRES * HRES) + B * 4 + ((h & 1) << 1) + (w & 1);
}

__device__ __forceinline__ void to_idx(float c, int size, int& i0, int& i1, float& w) {
    // align_corners=True mapping; w from UNCLIPPED floor (matches ref).
    float p = (c + 1.0f) * 0.5f * (float)(size - 1);
    float f = floorf(p);
    w = p - f;
    int i = (int)f;
    i0 = min(max(i, 0), size - 1);
    i1 = min(i0 + 1, size - 1);
}

__device__ __forceinline__ void acc_texel(float* acc, uint4 v, float w) {
    union { uint4 u; __half2 h[4]; } r; r.u = v;
    float2 f0 = __half22float2(r.h[0]);
    float2 f1 = __half22float2(r.h[1]);
    float2 f2 = __half22float2(r.h[2]);
    float2 f3 = __half22float2(r.h[3]);
    acc[0] = fmaf(w, f0.x, acc[0]); acc[1] = fmaf(w, f0.y, acc[1]);
    acc[2] = fmaf(w, f1.x, acc[2]); acc[3] = fmaf(w, f1.y, acc[3]);
    acc[4] = fmaf(w, f2.x, acc[4]); acc[5] = fmaf(w, f2.y, acc[5]);
    acc[6] = fmaf(w, f3.x, acc[6]); acc[7] = fmaf(w, f3.y, acc[7]);
}

__device__ __forceinline__ float get_bound(const int* bound_p) {
    int bi = __ldg(bound_p);
    return (bi > 0 && bi < 100000000) ? (float)bi : __int_as_float(bi);
}

// index range [lo, hi] of texels touchable by normalized coords in [cmin, cmax]
__device__ __forceinline__ void coord_range(float cmin, float cmax, int S,
                                            int& lo, int& hi) {
    float pmin = (cmin + 1.0f) * 0.5f * (float)(S - 1);
    float pmax = (cmax + 1.0f) * 0.5f * (float)(S - 1);
    lo = max((int)floorf(pmin) - 1, 0);
    hi = min((int)floorf(pmax) + 2, S - 1);
}

// ---------------------------------------------------------------------------
// K1: bbox reduction over xyz (grid-stride, warp-reduce, per-warp atomics)
// ---------------------------------------------------------------------------
__global__ void __launch_bounds__(256) bbox_kernel(const float* __restrict__ xyz, int N) {
    float mn[3] = { 1e30f,  1e30f,  1e30f};
    float mx[3] = {-1e30f, -1e30f, -1e30f};
    int stride = gridDim.x * blockDim.x;
    for (int n = blockIdx.x * blockDim.x + threadIdx.x; n < N; n += stride) {
#pragma unroll
        for (int d = 0; d < 3; d++) {
            float v = __ldg(xyz + 3 * n + d);
            mn[d] = fminf(mn[d], v);
            mx[d] = fmaxf(mx[d], v);
        }
    }
#pragma unroll
    for (int d = 0; d < 3; d++) {
#pragma unroll
        for (int o = 16; o > 0; o >>= 1) {
            mn[d] = fminf(mn[d], __shfl_xor_sync(0xffffffffu, mn[d], o));
            mx[d] = fmaxf(mx[d], __shfl_xor_sync(0xffffffffu, mx[d], o));
        }
    }
    if ((threadIdx.x & 31) == 0) {
#pragma unroll
        for (int d = 0; d < 3; d++) {
            atomicMin(&g_bbox_min[d], f2u_ord(mn[d]));
            atomicMax(&g_bbox_max[d], f2u_ord(mx[d]));
        }
    }
}

// ---------------------------------------------------------------------------
// K2: fused transpose, bbox-guarded, BLOCKED outputs.
// ---------------------------------------------------------------------------
__global__ void __launch_bounds__(256) transpose_all_kernel(
    const float* __restrict__ grid_in,
    const float* __restrict__ planes_in,
    const int* __restrict__ bound_p)
{
    const int VG = LRES * LRES * LRES;
    const int V2 = HRES * HRES;
    int t = blockIdx.x * blockDim.x + threadIdx.x;

    float inv = 1.0f / get_bound(bound_p);
    float nmin[3], nmax[3];
#pragma unroll
    for (int d = 0; d < 3; d++) {
        float a = u2f_ord(g_bbox_min[d]) * inv;
        float b = u2f_ord(g_bbox_max[d]) * inv;
        nmin[d] = fminf(a, b);
        nmax[d] = fmaxf(a, b);
    }

    if (t < VG) {
        int v = t;
        int x = v & (LRES - 1);
        int y = (v >> 7) & (LRES - 1);
        int z = v >> 14;
        int lo, hi;
        coord_range(nmin[0], nmax[0], LRES, lo, hi);
        if (x < lo || x > hi) return;
        coord_range(nmin[1], nmax[1], LRES, lo, hi);
        if (y < lo || y > hi) return;
        coord_range(nmin[2], nmax[2], LRES, lo, hi);
        if (z < lo || z > hi) return;

        float4 a, b;
        a.x = __ldg(grid_in + 0 * VG + v);
        a.y = __ldg(grid_in + 1 * VG + v);
        a.z = __ldg(grid_in + 2 * VG + v);
        a.w = __ldg(grid_in + 3 * VG + v);
        b.x = __ldg(grid_in + 4 * VG + v);
        b.y = __ldg(grid_in + 5 * VG + v);
        b.z = __ldg(grid_in + 6 * VG + v);
        b.w = __ldg(grid_in + 7 * VG + v);
        reinterpret_cast<uint4*>(g_grid_h)[gidx_blk(z, y, x)] = pack8_half(a, b);
    } else {
        int u = t - VG;
        if (u >= 3 * V2) return;
        int p = u / V2;
        int v = u - p * V2;
        int w = v & (HRES - 1);
        int h = v >> 10;

        // plane dim map: p0 (W=x,H=y), p1 (W=y,H=z), p2 (W=z,H=x)
        int wd = p;
        int hd = (p + 1) % 3;
        int lo, hi;
        coord_range(nmin[wd], nmax[wd], HRES, lo, hi);
        if (w < lo || w > hi) return;
        coord_range(nmin[hd], nmax[hd], HRES, lo, hi);
        if (h < lo || h > hi) return;

        const float* base = planes_in + (size_t)p * NCH * V2 + v;
        float4 a, b;
        a.x = __ldg(base + 0 * V2);
        a.y = __ldg(base + 1 * V2);
        a.z = __ldg(base + 2 * V2);
        a.w = __ldg(base + 3 * V2);
        b.x = __ldg(base + 4 * V2);
        b.y = __ldg(base + 5 * V2);
        b.z = __ldg(base + 6 * V2);
        b.w = __ldg(base + 7 * V2);
        reinterpret_cast<uint4*>(g_planes_h)[pidx_blk(p, h, w)] = pack8_half(a, b);
    }
}

// ---------------------------------------------------------------------------
// K3: 8-lane-per-point gather.
//   Phase A: lane s loads grid corner (dz,dy,dx)=bits(s) -> 1 instr,
//            E[lines] = 3.375/pt (2x2x2 block = 1 line).
//   Phase B: lanes 0-3 plane0 corners, lanes 4-7 plane1 corners -> 1 instr.
//   Phase C: lanes 0-3 plane2 corners -> 1 half-predicated instr.
//   Reduce: 3-step halving butterfly (7 SHFLs); lane s owns channel s.
//   Store: STG.32, warp = 4 points x 8 ch contiguous = 128B.
// ---------------------------------------------------------------------------
__global__ void __launch_bounds__(256) gather_kernel(
    const float* __restrict__ xyz,
    const int* __restrict__ bound_p,
    float* __restrict__ out,
    int N)
{
    // re-arm bbox for next replay (gather does not read it; transpose already did)
    if (blockIdx.x == 0 && threadIdx.x < 3) {
        g_bbox_min[threadIdx.x] = 0xFFFFFFFFu;
        g_bbox_max[threadIdx.x] = 0u;
    }

    int tid = blockIdx.x * blockDim.x + threadIdx.x;
    int n = tid >> 3;            // point index (8 lanes per point)
    int s = tid & 7;             // lane-in-group
    if (n >= N) return;          // whole group drops together

    float inv = 1.0f / get_bound(bound_p);
    float x = __ldg(xyz + 3 * n + 0) * inv;
    float y = __ldg(xyz + 3 * n + 1) * inv;
    float z = __ldg(xyz + 3 * n + 2) * inv;

    const uint4* GT = reinterpret_cast<const uint4*>(g_grid_h);
    const uint4* PT = reinterpret_cast<const uint4*>(g_planes_h);

    int x0, x1, y0, y1, z0, z1;
    float wx, wy, wz;
    to_idx(x, LRES, x0, x1, wx);
    to_idx(y, LRES, y0, y1, wy);
    to_idx(z, LRES, z0, z1, wz);

    int xh0, xh1, yh0, yh1, zh0, zh1;
    float wxh, wyh, wzh;
    to_idx(x, HRES, xh0, xh1, wxh);
    to_idx(y, HRES, yh0, yh1, wyh);
    to_idx(z, HRES, zh0, zh1, wzh);

    int dx = s & 1, dy = (s >> 1) & 1, dz = (s >> 2) & 1;

    float acc[NCH];
#pragma unroll
    for (int c = 0; c < NCH; c++) acc[c] = 0.0f;

    // ---- Phase A: grid corner (one LDG for all 8 corners across the group)
    {
        int gxi = dx ? x1 : x0;
        int gyi = dy ? y1 : y0;
        int gzi = dz ? z1 : z0;
        float wA = (dx ? wx : 1.0f - wx) * (dy ? wy : 1.0f - wy)
                 * (dz ? wz : 1.0f - wz);
        uint4 tA = __ldg(GT + gidx_blk(gzi, gyi, gxi));
        acc_texel(acc, tA, wA);
    }

    // ---- Phase B: planes 0 (lanes 0-3) and 1 (lanes 4-7), one LDG
    {
        int q = s >> 2;          // 0 -> plane0, 1 -> plane1
        int dw = dx, dh = dy;    // 2x2 corner within the plane
        int wi, hi_;
        float wB;
        if (q == 0) {            // plane0: W=x, H=y
            wi = dw ? xh1 : xh0;  hi_ = dh ? yh1 : yh0;
            wB = (dw ? wxh : 1.0f - wxh) * (dh ? wyh : 1.0f - wyh);
        } else {                 // plane1: W=y, H=z
            wi = dw ? yh1 : yh0;  hi_ = dh ? zh1 : zh0;
            wB = (dw ? wyh : 1.0f - wyh) * (dh ? wzh : 1.0f - wzh);
        }
        uint4 tB = __ldg(PT + pidx_blk(q, hi_, wi));
        acc_texel(acc, tB, wB);
    }

    // ---- Phase C: plane2 on lanes 0-3 (half-predicated LDG)
    if (s < 4) {                 // plane2: W=z, H=x
        int wi  = dx ? zh1 : zh0;
        int hi_ = dy ? xh1 : xh0;
        float wC = (dx ? wzh : 1.0f - wzh) * (dy ? wxh : 1.0f - wxh);
        uint4 tC = __ldg(PT + pidx_blk(2, hi_, wi));
        acc_texel(acc, tC, wC);
    }

    // ---- 3-step halving butterfly over the 8-lane group.
    // After step k each lane holds half as many channels, summed over 2x lanes.
    // Lane s finishes owning channel s.
    unsigned mask = __activemask();
    float t4[4];
#pragma unroll
    for (int j = 0; j < 4; j++) {
        float keep = (s & 4) ? acc[j + 4] : acc[j];
        float send = (s & 4) ? acc[j]     : acc[j + 4];
        t4[j] = keep + __shfl_xor_sync(mask, send, 4);
    }
    float t2[2];
#pragma unroll
    for (int j = 0; j < 2; j++) {
        float keep = (s & 2) ? t4[j + 2] : t4[j];
        float send = (s & 2) ? t4[j]     : t4[j + 2];
        t2[j] = keep + __shfl_xor_sync(mask, send, 2);
    }
    {
        float keep = (s & 1) ? t2[1] : t2[0];
        float send = (s & 1) ? t2[0] : t2[1];
        float res = keep + __shfl_xor_sync(mask, send, 1);
        out[(size_t)n * NCH + s] = res;   // warp: 4 pts x 8 ch = 128B contiguous
    }
}

extern "C" void kernel_launch(void* const* d_in, const int* in_sizes, int n_in,
                              void* d_out, int out_size) {
    const float* xyz   = (const float*)d_in[0];
    const int*   bound = (const int*)d_in[1];
    const float* Lg    = (const float*)d_in[2];
    const float* Hp    = (const float*)d_in[3];
    float* out = (float*)d_out;

    int N = in_sizes[0] / 3;

    bbox_kernel<<<512, 256>>>(xyz, N);

    const int VG = LRES * LRES * LRES;
    const int VT = VG + 3 * HRES * HRES;
    transpose_all_kernel<<<(VT + 255) / 256, 256>>>(Lg, Hp, bound);

    long long threads = 8LL * N;
    gather_kernel<<<(int)((threads + 255) / 256), 256>>>(xyz, bound, out, N);
}

// round 14
// speedup vs baseline: 1.2211x; 1.2211x over previous
#include <cuda_runtime.h>
#include <cuda_fp16.h>
#include <cuda_bf16.h>

#define LRES 128
#define HRES 1024
#define NCH 8

// Channel-innermost fp16 scratch (LINEAR layouts — proven best for
// per-instruction pair-lane line sharing). One texel = 16B = one LDG.128.
__device__ __half g_grid_h[LRES * LRES * LRES * NCH];    // [z][y][x][c]  32 MB
__device__ __half g_planes_h[3 * HRES * HRES * NCH];     // [p][h][w][c]  48 MB

// Global scalar bbox over ALL coords (order-preserving uint encoding of float).
// Statically initialized; re-armed inside gather_kernel for the next replay.
__device__ unsigned g_bbox_min = 0xFFFFFFFFu;
__device__ unsigned g_bbox_max = 0u;

__device__ __forceinline__ unsigned f2u_ord(float f) {
    unsigned u = __float_as_uint(f);
    return (u & 0x80000000u) ? ~u : (u | 0x80000000u);
}
__device__ __forceinline__ float u2f_ord(unsigned u) {
    return __uint_as_float((u & 0x80000000u) ? (u ^ 0x80000000u) : ~u);
}

__device__ __forceinline__ uint4 pack8_half(float4 a, float4 b) {
    union { uint4 u; __half2 h[4]; } r;
    r.h[0] = __floats2half2_rn(a.x, a.y);
    r.h[1] = __floats2half2_rn(a.z, a.w);
    r.h[2] = __floats2half2_rn(b.x, b.y);
    r.h[3] = __floats2half2_rn(b.z, b.w);
    return r.u;
}

__device__ __forceinline__ void to_idx(float c, int size, int& i0, int& i1, float& w) {
    // align_corners=True mapping; w from UNCLIPPED floor (matches ref).
    float p = (c + 1.0f) * 0.5f * (float)(size - 1);
    float f = floorf(p);
    w = p - f;
    int i = (int)f;
    i0 = min(max(i, 0), size - 1);
    i1 = min(i0 + 1, size - 1);
}

__device__ __forceinline__ void acc_texel(float* acc, uint4 v, float w) {
    union { uint4 u; __half2 h[4]; } r; r.u = v;
    float2 f0 = __half22float2(r.h[0]);
    float2 f1 = __half22float2(r.h[1]);
    float2 f2 = __half22float2(r.h[2]);
    float2 f3 = __half22float2(r.h[3]);
    acc[0] = fmaf(w, f0.x, acc[0]); acc[1] = fmaf(w, f0.y, acc[1]);
    acc[2] = fmaf(w, f1.x, acc[2]); acc[3] = fmaf(w, f1.y, acc[3]);
    acc[4] = fmaf(w, f2.x, acc[4]); acc[5] = fmaf(w, f2.y, acc[5]);
    acc[6] = fmaf(w, f3.x, acc[6]); acc[7] = fmaf(w, f3.y, acc[7]);
}

__device__ __forceinline__ float get_bound(const int* bound_p) {
    int bi = __ldg(bound_p);
    return (bi > 0 && bi < 100000000) ? (float)bi : __int_as_float(bi);
}

// index range [lo, hi] of texels touchable by normalized coords in [cmin, cmax]
__device__ __forceinline__ void coord_range(float cmin, float cmax, int S,
                                            int& lo, int& hi) {
    float pmin = (cmin + 1.0f) * 0.5f * (float)(S - 1);
    float pmax = (cmax + 1.0f) * 0.5f * (float)(S - 1);
    lo = max((int)floorf(pmin) - 1, 0);
    hi = min((int)floorf(pmax) + 2, S - 1);
}

// ---------------------------------------------------------------------------
// K1: flat scalar bbox over all 3N coords. float4 loads, 2-deep ILP,
// 4096 blocks for latency coverage. Conservative (dim-combined) but exact
// superset of the per-dim boxes -> transpose guard stays correct.
// ---------------------------------------------------------------------------
__global__ void __launch_bounds__(256) bbox_kernel(const float* __restrict__ xyz,
                                                   int M /* = 3*N floats */) {
    const float4* v4 = reinterpret_cast<const float4*>(xyz);
    int M4 = M >> 2;                       // full float4s
    float mn =  1e30f, mx = -1e30f;

    int i = blockIdx.x * blockDim.x + threadIdx.x;
    int stride = gridDim.x * blockDim.x;
    // 2-deep unrolled grid-stride for MLP
    for (; i + stride < M4; i += 2 * stride) {
        float4 a = __ldg(v4 + i);
        float4 b = __ldg(v4 + i + stride);
        mn = fminf(mn, fminf(fminf(a.x, a.y), fminf(a.z, a.w)));
        mx = fmaxf(mx, fmaxf(fmaxf(a.x, a.y), fmaxf(a.z, a.w)));
        mn = fminf(mn, fminf(fminf(b.x, b.y), fminf(b.z, b.w)));
        mx = fmaxf(mx, fmaxf(fmaxf(b.x, b.y), fmaxf(b.z, b.w)));
    }
    if (i < M4) {
        float4 a = __ldg(v4 + i);
        mn = fminf(mn, fminf(fminf(a.x, a.y), fminf(a.z, a.w)));
        mx = fmaxf(mx, fmaxf(fmaxf(a.x, a.y), fmaxf(a.z, a.w)));
    }
    // tail floats
    int t = (M4 << 2) + (blockIdx.x * blockDim.x + threadIdx.x);
    if (t < M) {
        float a = __ldg(xyz + t);
        mn = fminf(mn, a);
        mx = fmaxf(mx, a);
    }

#pragma unroll
    for (int o = 16; o > 0; o >>= 1) {
        mn = fminf(mn, __shfl_xor_sync(0xffffffffu, mn, o));
        mx = fmaxf(mx, __shfl_xor_sync(0xffffffffu, mx, o));
    }
    if ((threadIdx.x & 31) == 0) {
        atomicMin(&g_bbox_min, f2u_ord(mn));
        atomicMax(&g_bbox_max, f2u_ord(mx));
    }
}

// ---------------------------------------------------------------------------
// K2: fused transpose, bbox-guarded — only texels reachable by the points
// are transposed. Out-of-range threads exit before any gmem load.
// ---------------------------------------------------------------------------
__global__ void __launch_bounds__(256) transpose_all_kernel(
    const float* __restrict__ grid_in,
    const float* __restrict__ planes_in,
    const int* __restrict__ bound_p)
{
    const int VG = LRES * LRES * LRES;
    const int V2 = HRES * HRES;
    int t = blockIdx.x * blockDim.x + threadIdx.x;

    // normalized scalar bbox (handles negative bound by re-sorting)
    float inv = 1.0f / get_bound(bound_p);
    float a0 = u2f_ord(g_bbox_min) * inv;
    float b0 = u2f_ord(g_bbox_max) * inv;
    float nmin = fminf(a0, b0);
    float nmax = fmaxf(a0, b0);

    if (t < VG) {
        int v = t;
        int x = v & (LRES - 1);
        int y = (v >> 7) & (LRES - 1);
        int z = v >> 14;
        int lo, hi;
        coord_range(nmin, nmax, LRES, lo, hi);
        if (x < lo || x > hi || y < lo || y > hi || z < lo || z > hi) return;

        float4 a, b;
        a.x = __ldg(grid_in + 0 * VG + v);
        a.y = __ldg(grid_in + 1 * VG + v);
        a.z = __ldg(grid_in + 2 * VG + v);
        a.w = __ldg(grid_in + 3 * VG + v);
        b.x = __ldg(grid_in + 4 * VG + v);
        b.y = __ldg(grid_in + 5 * VG + v);
        b.z = __ldg(grid_in + 6 * VG + v);
        b.w = __ldg(grid_in + 7 * VG + v);
        reinterpret_cast<uint4*>(g_grid_h)[v] = pack8_half(a, b);
    } else {
        int u = t - VG;
        if (u >= 3 * V2) return;
        int p = u / V2;
        int v = u - p * V2;
        int w = v & (HRES - 1);
        int h = v >> 10;

        int lo, hi;
        coord_range(nmin, nmax, HRES, lo, hi);
        if (w < lo || w > hi || h < lo || h > hi) return;

        const float* base = planes_in + (size_t)p * NCH * V2 + v;
        float4 a, b;
        a.x = __ldg(base + 0 * V2);
        a.y = __ldg(base + 1 * V2);
        a.z = __ldg(base + 2 * V2);
        a.w = __ldg(base + 3 * V2);
        b.x = __ldg(base + 4 * V2);
        b.y = __ldg(base + 5 * V2);
        b.z = __ldg(base + 6 * V2);
        b.w = __ldg(base + 7 * V2);
        reinterpret_cast<uint4*>(g_planes_h)[u] = pack8_half(a, b);
    }
}

// ---------------------------------------------------------------------------
// K3: pair-lane gather (byte-identical logic to the proven 89.2 µs version).
// Lanes (2i, 2i+1) share point i; lane r handles W index x_r.
// 10 LDG.128/lane, half-exchange via 4 SHFL.BFLY, contiguous 16B store.
// ---------------------------------------------------------------------------
__global__ void __launch_bounds__(256) gather_kernel(
    const float* __restrict__ xyz,
    const int* __restrict__ bound_p,
    float* __restrict__ out,
    int N)
{
    // re-arm bbox for next replay (transpose already consumed it)
    if (blockIdx.x == 0 && threadIdx.x == 0) {
        g_bbox_min = 0xFFFFFFFFu;
        g_bbox_max = 0u;
    }

    int tid = blockIdx.x * blockDim.x + threadIdx.x;
    int n = tid >> 1;            // point index (2 lanes per point)
    int r = tid & 1;             // 0: low W index, 1: high W index
    if (n >= N) return;

    float inv = 1.0f / get_bound(bound_p);
    float x = __ldg(xyz + 3 * n + 0) * inv;
    float y = __ldg(xyz + 3 * n + 1) * inv;
    float z = __ldg(xyz + 3 * n + 2) * inv;

    const uint4* GT = reinterpret_cast<const uint4*>(g_grid_h);
    const uint4* PT = reinterpret_cast<const uint4*>(g_planes_h);

    int x0, x1, y0, y1, z0, z1;
    float wx, wy, wz;
    to_idx(x, LRES, x0, x1, wx);
    to_idx(y, LRES, y0, y1, wy);
    to_idx(z, LRES, z0, z1, wz);

    int xh0, xh1, yh0, yh1, zh0, zh1;
    float wxh, wyh, wzh;
    to_idx(x, HRES, xh0, xh1, wxh);
    to_idx(y, HRES, yh0, yh1, wyh);
    to_idx(z, HRES, zh0, zh1, wzh);

    int   gx  = r ? x1  : x0;   float wgx = r ? wx  : 1.0f - wx;
    int   p0x = r ? xh1 : xh0;  float w0x = r ? wxh : 1.0f - wxh;  // plane0 W = x
    int   p1y = r ? yh1 : yh0;  float w1y = r ? wyh : 1.0f - wyh;  // plane1 W = y
    int   p2z = r ? zh1 : zh0;  float w2z = r ? wzh : 1.0f - wzh;  // plane2 W = z

    #define GIDX(zz, yy) (((zz) * LRES + (yy)) * LRES + gx)
    uint4 g00 = __ldg(GT + GIDX(z0, y0));
    uint4 g01 = __ldg(GT + GIDX(z0, y1));
    uint4 g10 = __ldg(GT + GIDX(z1, y0));
    uint4 g11 = __ldg(GT + GIDX(z1, y1));
    #undef GIDX
    #define PIDX(p, hh, ww) ((p) * (HRES * HRES) + (hh) * HRES + (ww))
    uint4 pa0 = __ldg(PT + PIDX(0, yh0, p0x));
    uint4 pa1 = __ldg(PT + PIDX(0, yh1, p0x));
    uint4 pb0 = __ldg(PT + PIDX(1, zh0, p1y));
    uint4 pb1 = __ldg(PT + PIDX(1, zh1, p1y));
    uint4 pc0 = __ldg(PT + PIDX(2, xh0, p2z));
    uint4 pc1 = __ldg(PT + PIDX(2, xh1, p2z));
    #undef PIDX

    float acc[NCH];
#pragma unroll
    for (int c = 0; c < NCH; c++) acc[c] = 0.0f;

    {
        float uy = 1.0f - wy, uz = 1.0f - wz;
        acc_texel(acc, g00, uz * uy * wgx);
        acc_texel(acc, g01, uz * wy * wgx);
        acc_texel(acc, g10, wz * uy * wgx);
        acc_texel(acc, g11, wz * wy * wgx);
    }
    acc_texel(acc, pa0, (1.0f - wyh) * w0x);   // plane0: H = y
    acc_texel(acc, pa1, wyh * w0x);
    acc_texel(acc, pb0, (1.0f - wzh) * w1y);   // plane1: H = z
    acc_texel(acc, pb1, wzh * w1y);
    acc_texel(acc, pc0, (1.0f - wxh) * w2z);   // plane2: H = x
    acc_texel(acc, pc1, wxh * w2z);

    // half exchange: 4 SHFLs, each lane sends the half it doesn't keep
    unsigned mask = __activemask();
    float res[4];
#pragma unroll
    for (int c = 0; c < 4; c++) {
        float keep = r ? acc[c + 4] : acc[c];
        float send = r ? acc[c]     : acc[c + 4];
        res[c] = keep + __shfl_xor_sync(mask, send, 1);
    }

    reinterpret_cast<float4*>(out)[(size_t)n * 2 + r] =
        make_float4(res[0], res[1], res[2], res[3]);
}

extern "C" void kernel_launch(void* const* d_in, const int* in_sizes, int n_in,
                              void* d_out, int out_size) {
    const float* xyz   = (const float*)d_in[0];
    const int*   bound = (const int*)d_in[1];
    const float* Lg    = (const float*)d_in[2];
    const float* Hp    = (const float*)d_in[3];
    float* out = (float*)d_out;

    int N = in_sizes[0] / 3;
    int M = in_sizes[0];       // total floats in xyz

    bbox_kernel<<<4096, 256>>>(xyz, M);

    const int VG = LRES * LRES * LRES;
    const int VT = VG + 3 * HRES * HRES;
    transpose_all_kernel<<<(VT + 255) / 256, 256>>>(Lg, Hp, bound);

    gather_kernel<<<(2 * N + 255) / 256, 256>>>(xyz, bound, out, N);
}

// round 15
// speedup vs baseline: 1.4063x; 1.1516x over previous
#include <cuda_runtime.h>
#include <cuda_fp16.h>
#include <cuda_bf16.h>

#define LRES 128
#define HRES 1024
#define NCH 8

// Channel-innermost fp16 scratch (LINEAR layouts — proven best for
// per-instruction pair-lane line sharing). One texel = 16B = one LDG.128.
__device__ __half g_grid_h[LRES * LRES * LRES * NCH];    // [z][y][x][c]  32 MB
__device__ __half g_planes_h[3 * HRES * HRES * NCH];     // [p][h][w][c]  48 MB

// Global scalar bbox over ALL coords (order-preserving uint encoding of float).
// Statically initialized; re-armed inside gather_kernel for the next replay.
__device__ unsigned g_bbox_min = 0xFFFFFFFFu;
__device__ unsigned g_bbox_max = 0u;

__device__ __forceinline__ unsigned f2u_ord(float f) {
    unsigned u = __float_as_uint(f);
    return (u & 0x80000000u) ? ~u : (u | 0x80000000u);
}
__device__ __forceinline__ float u2f_ord(unsigned u) {
    return __uint_as_float((u & 0x80000000u) ? (u ^ 0x80000000u) : ~u);
}

__device__ __forceinline__ uint4 pack8_half(float4 a, float4 b) {
    union { uint4 u; __half2 h[4]; } r;
    r.h[0] = __floats2half2_rn(a.x, a.y);
    r.h[1] = __floats2half2_rn(a.z, a.w);
    r.h[2] = __floats2half2_rn(b.x, b.y);
    r.h[3] = __floats2half2_rn(b.z, b.w);
    return r.u;
}

__device__ __forceinline__ void to_idx(float c, int size, int& i0, int& i1, float& w) {
    // align_corners=True mapping; w from UNCLIPPED floor (matches ref).
    float p = (c + 1.0f) * 0.5f * (float)(size - 1);
    float f = floorf(p);
    w = p - f;
    int i = (int)f;
    i0 = min(max(i, 0), size - 1);
    i1 = min(i0 + 1, size - 1);
}

__device__ __forceinline__ void acc_texel(float* acc, uint4 v, float w) {
    union { uint4 u; __half2 h[4]; } r; r.u = v;
    float2 f0 = __half22float2(r.h[0]);
    float2 f1 = __half22float2(r.h[1]);
    float2 f2 = __half22float2(r.h[2]);
    float2 f3 = __half22float2(r.h[3]);
    acc[0] = fmaf(w, f0.x, acc[0]); acc[1] = fmaf(w, f0.y, acc[1]);
    acc[2] = fmaf(w, f1.x, acc[2]); acc[3] = fmaf(w, f1.y, acc[3]);
    acc[4] = fmaf(w, f2.x, acc[4]); acc[5] = fmaf(w, f2.y, acc[5]);
    acc[6] = fmaf(w, f3.x, acc[6]); acc[7] = fmaf(w, f3.y, acc[7]);
}

__device__ __forceinline__ float get_bound(const int* bound_p) {
    int bi = __ldg(bound_p);
    return (bi > 0 && bi < 100000000) ? (float)bi : __int_as_float(bi);
}

// index range [lo, hi] of texels touchable by normalized coords in [cmin, cmax]
__device__ __forceinline__ void coord_range(float cmin, float cmax, int S,
                                            int& lo, int& hi) {
    float pmin = (cmin + 1.0f) * 0.5f * (float)(S - 1);
    float pmax = (cmax + 1.0f) * 0.5f * (float)(S - 1);
    lo = max((int)floorf(pmin) - 1, 0);
    hi = min((int)floorf(pmax) + 2, S - 1);
}

// ---------------------------------------------------------------------------
// K1: flat scalar bbox over all 3N coords. float4 loads, grid-stride,
// warp reduce -> SMEM block reduce -> TWO atomics per block (not per warp).
// R13's regression was 64K single-address atomics; this emits 2K total.
// ---------------------------------------------------------------------------
__global__ void __launch_bounds__(256) bbox_kernel(const float* __restrict__ xyz,
                                                   int M /* = 3*N floats */) {
    __shared__ float s_mn[8], s_mx[8];
    const float4* v4 = reinterpret_cast<const float4*>(xyz);
    int M4 = M >> 2;
    float mn =  1e30f, mx = -1e30f;

    int stride = gridDim.x * blockDim.x;
    for (int i = blockIdx.x * blockDim.x + threadIdx.x; i < M4; i += stride) {
        float4 a = __ldg(v4 + i);
        mn = fminf(mn, fminf(fminf(a.x, a.y), fminf(a.z, a.w)));
        mx = fmaxf(mx, fmaxf(fmaxf(a.x, a.y), fmaxf(a.z, a.w)));
    }
    // tail floats (M not divisible by 4)
    int t = (M4 << 2) + blockIdx.x * blockDim.x + threadIdx.x;
    if (t < M) {
        float a = __ldg(xyz + t);
        mn = fminf(mn, a);
        mx = fmaxf(mx, a);
    }

#pragma unroll
    for (int o = 16; o > 0; o >>= 1) {
        mn = fminf(mn, __shfl_xor_sync(0xffffffffu, mn, o));
        mx = fmaxf(mx, __shfl_xor_sync(0xffffffffu, mx, o));
    }
    int wid = threadIdx.x >> 5;
    if ((threadIdx.x & 31) == 0) { s_mn[wid] = mn; s_mx[wid] = mx; }
    __syncthreads();
    if (threadIdx.x == 0) {
        float bmn = s_mn[0], bmx = s_mx[0];
#pragma unroll
        for (int w = 1; w < 8; w++) {
            bmn = fminf(bmn, s_mn[w]);
            bmx = fmaxf(bmx, s_mx[w]);
        }
        atomicMin(&g_bbox_min, f2u_ord(bmn));
        atomicMax(&g_bbox_max, f2u_ord(bmx));
    }
}

// ---------------------------------------------------------------------------
// K2: fused transpose, bbox-guarded — only texels reachable by the points
// are transposed. Out-of-range threads exit before any gmem load.
// ---------------------------------------------------------------------------
__global__ void __launch_bounds__(256) transpose_all_kernel(
    const float* __restrict__ grid_in,
    const float* __restrict__ planes_in,
    const int* __restrict__ bound_p)
{
    const int VG = LRES * LRES * LRES;
    const int V2 = HRES * HRES;
    int t = blockIdx.x * blockDim.x + threadIdx.x;

    // normalized scalar bbox (handles negative bound by re-sorting)
    float inv = 1.0f / get_bound(bound_p);
    float a0 = u2f_ord(g_bbox_min) * inv;
    float b0 = u2f_ord(g_bbox_max) * inv;
    float nmin = fminf(a0, b0);
    float nmax = fmaxf(a0, b0);

    if (t < VG) {
        int v = t;
        int x = v & (LRES - 1);
        int y = (v >> 7) & (LRES - 1);
        int z = v >> 14;
        int lo, hi;
        coord_range(nmin, nmax, LRES, lo, hi);
        if (x < lo || x > hi || y < lo || y > hi || z < lo || z > hi) return;

        float4 a, b;
        a.x = __ldg(grid_in + 0 * VG + v);
        a.y = __ldg(grid_in + 1 * VG + v);
        a.z = __ldg(grid_in + 2 * VG + v);
        a.w = __ldg(grid_in + 3 * VG + v);
        b.x = __ldg(grid_in + 4 * VG + v);
        b.y = __ldg(grid_in + 5 * VG + v);
        b.z = __ldg(grid_in + 6 * VG + v);
        b.w = __ldg(grid_in + 7 * VG + v);
        reinterpret_cast<uint4*>(g_grid_h)[v] = pack8_half(a, b);
    } else {
        int u = t - VG;
        if (u >= 3 * V2) return;
        int p = u / V2;
        int v = u - p * V2;
        int w = v & (HRES - 1);
        int h = v >> 10;

        int lo, hi;
        coord_range(nmin, nmax, HRES, lo, hi);
        if (w < lo || w > hi || h < lo || h > hi) return;

        const float* base = planes_in + (size_t)p * NCH * V2 + v;
        float4 a, b;
        a.x = __ldg(base + 0 * V2);
        a.y = __ldg(base + 1 * V2);
        a.z = __ldg(base + 2 * V2);
        a.w = __ldg(base + 3 * V2);
        b.x = __ldg(base + 4 * V2);
        b.y = __ldg(base + 5 * V2);
        b.z = __ldg(base + 6 * V2);
        b.w = __ldg(base + 7 * V2);
        reinterpret_cast<uint4*>(g_planes_h)[u] = pack8_half(a, b);
    }
}

// ---------------------------------------------------------------------------
// K3: pair-lane gather (byte-identical logic to the proven 89.2 µs version).
// Lanes (2i, 2i+1) share point i; lane r handles W index x_r.
// 10 LDG.128/lane, half-exchange via 4 SHFL.BFLY, contiguous 16B store.
// ---------------------------------------------------------------------------
__global__ void __launch_bounds__(256) gather_kernel(
    const float* __restrict__ xyz,
    const int* __restrict__ bound_p,
    float* __restrict__ out,
    int N)
{
    // re-arm bbox for next replay (transpose already consumed it)
    if (blockIdx.x == 0 && threadIdx.x == 0) {
        g_bbox_min = 0xFFFFFFFFu;
        g_bbox_max = 0u;
    }

    int tid = blockIdx.x * blockDim.x + threadIdx.x;
    int n = tid >> 1;            // point index (2 lanes per point)
    int r = tid & 1;             // 0: low W index, 1: high W index
    if (n >= N) return;

    float inv = 1.0f / get_bound(bound_p);
    float x = __ldg(xyz + 3 * n + 0) * inv;
    float y = __ldg(xyz + 3 * n + 1) * inv;
    float z = __ldg(xyz + 3 * n + 2) * inv;

    const uint4* GT = reinterpret_cast<const uint4*>(g_grid_h);
    const uint4* PT = reinterpret_cast<const uint4*>(g_planes_h);

    int x0, x1, y0, y1, z0, z1;
    float wx, wy, wz;
    to_idx(x, LRES, x0, x1, wx);
    to_idx(y, LRES, y0, y1, wy);
    to_idx(z, LRES, z0, z1, wz);

    int xh0, xh1, yh0, yh1, zh0, zh1;
    float wxh, wyh, wzh;
    to_idx(x, HRES, xh0, xh1, wxh);
    to_idx(y, HRES, yh0, yh1, wyh);
    to_idx(z, HRES, zh0, zh1, wzh);

    int   gx  = r ? x1  : x0;   float wgx = r ? wx  : 1.0f - wx;
    int   p0x = r ? xh1 : xh0;  float w0x = r ? wxh : 1.0f - wxh;  // plane0 W = x
    int   p1y = r ? yh1 : yh0;  float w1y = r ? wyh : 1.0f - wyh;  // plane1 W = y
    int   p2z = r ? zh1 : zh0;  float w2z = r ? wzh : 1.0f - wzh;  // plane2 W = z

    #define GIDX(zz, yy) (((zz) * LRES + (yy)) * LRES + gx)
    uint4 g00 = __ldg(GT + GIDX(z0, y0));
    uint4 g01 = __ldg(GT + GIDX(z0, y1));
    uint4 g10 = __ldg(GT + GIDX(z1, y0));
    uint4 g11 = __ldg(GT + GIDX(z1, y1));
    #undef GIDX
    #define PIDX(p, hh, ww) ((p) * (HRES * HRES) + (hh) * HRES + (ww))
    uint4 pa0 = __ldg(PT + PIDX(0, yh0, p0x));
    uint4 pa1 = __ldg(PT + PIDX(0, yh1, p0x));
    uint4 pb0 = __ldg(PT + PIDX(1, zh0, p1y));
    uint4 pb1 = __ldg(PT + PIDX(1, zh1, p1y));
    uint4 pc0 = __ldg(PT + PIDX(2, xh0, p2z));
    uint4 pc1 = __ldg(PT + PIDX(2, xh1, p2z));
    #undef PIDX

    float acc[NCH];
#pragma unroll
    for (int c = 0; c < NCH; c++) acc[c] = 0.0f;

    {
        float uy = 1.0f - wy, uz = 1.0f - wz;
        acc_texel(acc, g00, uz * uy * wgx);
        acc_texel(acc, g01, uz * wy * wgx);
        acc_texel(acc, g10, wz * uy * wgx);
        acc_texel(acc, g11, wz * wy * wgx);
    }
    acc_texel(acc, pa0, (1.0f - wyh) * w0x);   // plane0: H = y
    acc_texel(acc, pa1, wyh * w0x);
    acc_texel(acc, pb0, (1.0f - wzh) * w1y);   // plane1: H = z
    acc_texel(acc, pb1, wzh * w1y);
    acc_texel(acc, pc0, (1.0f - wxh) * w2z);   // plane2: H = x
    acc_texel(acc, pc1, wxh * w2z);

    // half exchange: 4 SHFLs, each lane sends the half it doesn't keep
    unsigned mask = __activemask();
    float res[4];
#pragma unroll
    for (int c = 0; c < 4; c++) {
        float keep = r ? acc[c + 4] : acc[c];
        float send = r ? acc[c]     : acc[c + 4];
        res[c] = keep + __shfl_xor_sync(mask, send, 1);
    }

    reinterpret_cast<float4*>(out)[(size_t)n * 2 + r] =
        make_float4(res[0], res[1], res[2], res[3]);
}

extern "C" void kernel_launch(void* const* d_in, const int* in_sizes, int n_in,
                              void* d_out, int out_size) {
    const float* xyz   = (const float*)d_in[0];
    const int*   bound = (const int*)d_in[1];
    const float* Lg    = (const float*)d_in[2];
    const float* Hp    = (const float*)d_in[3];
    float* out = (float*)d_out;

    int N = in_sizes[0] / 3;
    int M = in_sizes[0];       // total floats in xyz

    bbox_kernel<<<1024, 256>>>(xyz, M);

    const int VG = LRES * LRES * LRES;
    const int VT = VG + 3 * HRES * HRES;
    transpose_all_kernel<<<(VT + 255) / 256, 256>>>(Lg, Hp, bound);

    gather_kernel<<<(2 * N + 255) / 256, 256>>>(xyz, bound, out, N);
}

// round 16
// speedup vs baseline: 1.4751x; 1.0489x over previous
#include <cuda_runtime.h>
#include <cuda_fp16.h>
#include <cuda_bf16.h>

#define LRES 128
#define HRES 1024
#define NCH 8

// Channel-innermost fp16 scratch (LINEAR layouts — proven best for
// per-instruction pair-lane line sharing). One texel = 16B = one LDG.128.
__device__ __half g_grid_h[LRES * LRES * LRES * NCH];    // [z][y][x][c]  32 MB
__device__ __half g_planes_h[3 * HRES * HRES * NCH];     // [p][h][w][c]  48 MB

// Global scalar bbox over ALL coords (order-preserving uint encoding of float).
// Statically initialized; re-armed inside gather_kernel for the next replay.
__device__ unsigned g_bbox_min = 0xFFFFFFFFu;
__device__ unsigned g_bbox_max = 0u;

__device__ __forceinline__ unsigned f2u_ord(float f) {
    unsigned u = __float_as_uint(f);
    return (u & 0x80000000u) ? ~u : (u | 0x80000000u);
}
__device__ __forceinline__ float u2f_ord(unsigned u) {
    return __uint_as_float((u & 0x80000000u) ? (u ^ 0x80000000u) : ~u);
}

__device__ __forceinline__ uint4 pack8_half(float4 a, float4 b) {
    union { uint4 u; __half2 h[4]; } r;
    r.h[0] = __floats2half2_rn(a.x, a.y);
    r.h[1] = __floats2half2_rn(a.z, a.w);
    r.h[2] = __floats2half2_rn(b.x, b.y);
    r.h[3] = __floats2half2_rn(b.z, b.w);
    return r.u;
}

__device__ __forceinline__ void to_idx(float c, int size, int& i0, int& i1, float& w) {
    // align_corners=True mapping; w from UNCLIPPED floor (matches ref).
    float p = (c + 1.0f) * 0.5f * (float)(size - 1);
    float f = floorf(p);
    w = p - f;
    int i = (int)f;
    i0 = min(max(i, 0), size - 1);
    i1 = min(i0 + 1, size - 1);
}

__device__ __forceinline__ void acc_texel(float* acc, uint4 v, float w) {
    union { uint4 u; __half2 h[4]; } r; r.u = v;
    float2 f0 = __half22float2(r.h[0]);
    float2 f1 = __half22float2(r.h[1]);
    float2 f2 = __half22float2(r.h[2]);
    float2 f3 = __half22float2(r.h[3]);
    acc[0] = fmaf(w, f0.x, acc[0]); acc[1] = fmaf(w, f0.y, acc[1]);
    acc[2] = fmaf(w, f1.x, acc[2]); acc[3] = fmaf(w, f1.y, acc[3]);
    acc[4] = fmaf(w, f2.x, acc[4]); acc[5] = fmaf(w, f2.y, acc[5]);
    acc[6] = fmaf(w, f3.x, acc[6]); acc[7] = fmaf(w, f3.y, acc[7]);
}

__device__ __forceinline__ float get_bound(const int* bound_p) {
    int bi = __ldg(bound_p);
    return (bi > 0 && bi < 100000000) ? (float)bi : __int_as_float(bi);
}

// index range [lo, hi] of texels touchable by normalized coords in [cmin, cmax]
__device__ __forceinline__ void coord_range(float cmin, float cmax, int S,
                                            int& lo, int& hi) {
    float pmin = (cmin + 1.0f) * 0.5f * (float)(S - 1);
    float pmax = (cmax + 1.0f) * 0.5f * (float)(S - 1);
    lo = max((int)floorf(pmin) - 1, 0);
    hi = min((int)floorf(pmax) + 2, S - 1);
}

// ---------------------------------------------------------------------------
// K1: flat scalar bbox. float4 loads, 2-deep ILP (independent accumulator
// pairs), warp reduce -> SMEM block reduce -> 2 atomics per block.
// ---------------------------------------------------------------------------
__global__ void __launch_bounds__(256) bbox_kernel(const float* __restrict__ xyz,
                                                   int M /* = 3*N floats */) {
    __shared__ float s_mn[8], s_mx[8];
    const float4* v4 = reinterpret_cast<const float4*>(xyz);
    int M4 = M >> 2;
    float mn0 =  1e30f, mx0 = -1e30f;
    float mn1 =  1e30f, mx1 = -1e30f;

    int stride = gridDim.x * blockDim.x;
    int i = blockIdx.x * blockDim.x + threadIdx.x;
    for (; i + stride < M4; i += 2 * stride) {
        float4 a = __ldg(v4 + i);
        float4 b = __ldg(v4 + i + stride);
        mn0 = fminf(mn0, fminf(fminf(a.x, a.y), fminf(a.z, a.w)));
        mx0 = fmaxf(mx0, fmaxf(fmaxf(a.x, a.y), fmaxf(a.z, a.w)));
        mn1 = fminf(mn1, fminf(fminf(b.x, b.y), fminf(b.z, b.w)));
        mx1 = fmaxf(mx1, fmaxf(fmaxf(b.x, b.y), fmaxf(b.z, b.w)));
    }
    if (i < M4) {
        float4 a = __ldg(v4 + i);
        mn0 = fminf(mn0, fminf(fminf(a.x, a.y), fminf(a.z, a.w)));
        mx0 = fmaxf(mx0, fmaxf(fmaxf(a.x, a.y), fmaxf(a.z, a.w)));
    }
    float mn = fminf(mn0, mn1), mx = fmaxf(mx0, mx1);

    // tail floats (M not divisible by 4)
    int t = (M4 << 2) + blockIdx.x * blockDim.x + threadIdx.x;
    if (t < M) {
        float a = __ldg(xyz + t);
        mn = fminf(mn, a);
        mx = fmaxf(mx, a);
    }

#pragma unroll
    for (int o = 16; o > 0; o >>= 1) {
        mn = fminf(mn, __shfl_xor_sync(0xffffffffu, mn, o));
        mx = fmaxf(mx, __shfl_xor_sync(0xffffffffu, mx, o));
    }
    int wid = threadIdx.x >> 5;
    if ((threadIdx.x & 31) == 0) { s_mn[wid] = mn; s_mx[wid] = mx; }
    __syncthreads();
    if (threadIdx.x == 0) {
        float bmn = s_mn[0], bmx = s_mx[0];
#pragma unroll
        for (int w = 1; w < 8; w++) {
            bmn = fminf(bmn, s_mn[w]);
            bmx = fmaxf(bmx, s_mx[w]);
        }
        atomicMin(&g_bbox_min, f2u_ord(bmn));
        atomicMax(&g_bbox_max, f2u_ord(bmx));
    }
}

// ---------------------------------------------------------------------------
// K2: COMPACTED transpose — fixed grid, device-computed bbox region,
// grid-stride over in-region texels ONLY (no guard-exit waste).
// ---------------------------------------------------------------------------
__global__ void __launch_bounds__(256) transpose_all_kernel(
    const float* __restrict__ grid_in,
    const float* __restrict__ planes_in,
    const int* __restrict__ bound_p)
{
    const int VG = LRES * LRES * LRES;
    const int V2 = HRES * HRES;

    float inv = 1.0f / get_bound(bound_p);
    float a0 = u2f_ord(g_bbox_min) * inv;
    float b0 = u2f_ord(g_bbox_max) * inv;
    float nmin = fminf(a0, b0);
    float nmax = fmaxf(a0, b0);

    int glo, ghi, hlo, hhi;
    coord_range(nmin, nmax, LRES, glo, ghi);
    coord_range(nmin, nmax, HRES, hlo, hhi);
    int GW = ghi - glo + 1;            // grid region edge
    int HW = hhi - hlo + 1;            // plane region edge
    int Vg = GW * GW * GW;             // grid region texels
    int Vp = HW * HW;                  // per-plane region texels
    int T  = Vg + 3 * Vp;

    int stride = gridDim.x * blockDim.x;
    for (int idx = blockIdx.x * blockDim.x + threadIdx.x; idx < T; idx += stride) {
        if (idx < Vg) {
            int dx = idx % GW;
            int rem = idx / GW;
            int dy = rem % GW;
            int dz = rem / GW;
            int x = glo + dx, y = glo + dy, z = glo + dz;
            int v = ((z * LRES) + y) * LRES + x;
            float4 a, b;
            a.x = __ldg(grid_in + 0 * VG + v);
            a.y = __ldg(grid_in + 1 * VG + v);
            a.z = __ldg(grid_in + 2 * VG + v);
            a.w = __ldg(grid_in + 3 * VG + v);
            b.x = __ldg(grid_in + 4 * VG + v);
            b.y = __ldg(grid_in + 5 * VG + v);
            b.z = __ldg(grid_in + 6 * VG + v);
            b.w = __ldg(grid_in + 7 * VG + v);
            reinterpret_cast<uint4*>(g_grid_h)[v] = pack8_half(a, b);
        } else {
            int u = idx - Vg;
            int p = u / Vp;
            int q = u - p * Vp;
            int w = hlo + (q % HW);
            int h = hlo + (q / HW);
            int v = h * HRES + w;
            const float* base = planes_in + (size_t)p * NCH * V2 + v;
            float4 a, b;
            a.x = __ldg(base + 0 * V2);
            a.y = __ldg(base + 1 * V2);
            a.z = __ldg(base + 2 * V2);
            a.w = __ldg(base + 3 * V2);
            b.x = __ldg(base + 4 * V2);
            b.y = __ldg(base + 5 * V2);
            b.z = __ldg(base + 6 * V2);
            b.w = __ldg(base + 7 * V2);
            reinterpret_cast<uint4*>(g_planes_h)[p * V2 + v] = pack8_half(a, b);
        }
    }
}

// ---------------------------------------------------------------------------
// K3: pair-lane gather (byte-identical logic to the proven 89.2 µs version).
// Lanes (2i, 2i+1) share point i; lane r handles W index x_r.
// 10 LDG.128/lane, half-exchange via 4 SHFL.BFLY, contiguous 16B store.
// ---------------------------------------------------------------------------
__global__ void __launch_bounds__(256) gather_kernel(
    const float* __restrict__ xyz,
    const int* __restrict__ bound_p,
    float* __restrict__ out,
    int N)
{
    // re-arm bbox for next replay (transpose already consumed it)
    if (blockIdx.x == 0 && threadIdx.x == 0) {
        g_bbox_min = 0xFFFFFFFFu;
        g_bbox_max = 0u;
    }

    int tid = blockIdx.x * blockDim.x + threadIdx.x;
    int n = tid >> 1;            // point index (2 lanes per point)
    int r = tid & 1;             // 0: low W index, 1: high W index
    if (n >= N) return;

    float inv = 1.0f / get_bound(bound_p);
    float x = __ldg(xyz + 3 * n + 0) * inv;
    float y = __ldg(xyz + 3 * n + 1) * inv;
    float z = __ldg(xyz + 3 * n + 2) * inv;

    const uint4* GT = reinterpret_cast<const uint4*>(g_grid_h);
    const uint4* PT = reinterpret_cast<const uint4*>(g_planes_h);

    int x0, x1, y0, y1, z0, z1;
    float wx, wy, wz;
    to_idx(x, LRES, x0, x1, wx);
    to_idx(y, LRES, y0, y1, wy);
    to_idx(z, LRES, z0, z1, wz);

    int xh0, xh1, yh0, yh1, zh0, zh1;
    float wxh, wyh, wzh;
    to_idx(x, HRES, xh0, xh1, wxh);
    to_idx(y, HRES, yh0, yh1, wyh);
    to_idx(z, HRES, zh0, zh1, wzh);

    int   gx  = r ? x1  : x0;   float wgx = r ? wx  : 1.0f - wx;
    int   p0x = r ? xh1 : xh0;  float w0x = r ? wxh : 1.0f - wxh;  // plane0 W = x
    int   p1y = r ? yh1 : yh0;  float w1y = r ? wyh : 1.0f - wyh;  // plane1 W = y
    int   p2z = r ? zh1 : zh0;  float w2z = r ? wzh : 1.0f - wzh;  // plane2 W = z

    #define GIDX(zz, yy) (((zz) * LRES + (yy)) * LRES + gx)
    uint4 g00 = __ldg(GT + GIDX(z0, y0));
    uint4 g01 = __ldg(GT + GIDX(z0, y1));
    uint4 g10 = __ldg(GT + GIDX(z1, y0));
    uint4 g11 = __ldg(GT + GIDX(z1, y1));
    #undef GIDX
    #define PIDX(p, hh, ww) ((p) * (HRES * HRES) + (hh) * HRES + (ww))
    uint4 pa0 = __ldg(PT + PIDX(0, yh0, p0x));
    uint4 pa1 = __ldg(PT + PIDX(0, yh1, p0x));
    uint4 pb0 = __ldg(PT + PIDX(1, zh0, p1y));
    uint4 pb1 = __ldg(PT + PIDX(1, zh1, p1y));
    uint4 pc0 = __ldg(PT + PIDX(2, xh0, p2z));
    uint4 pc1 = __ldg(PT + PIDX(2, xh1, p2z));
    #undef PIDX

    float acc[NCH];
#pragma unroll
    for (int c = 0; c < NCH; c++) acc[c] = 0.0f;

    {
        float uy = 1.0f - wy, uz = 1.0f - wz;
        acc_texel(acc, g00, uz * uy * wgx);
        acc_texel(acc, g01, uz * wy * wgx);
        acc_texel(acc, g10, wz * uy * wgx);
        acc_texel(acc, g11, wz * wy * wgx);
    }
    acc_texel(acc, pa0, (1.0f - wyh) * w0x);   // plane0: H = y
    acc_texel(acc, pa1, wyh * w0x);
    acc_texel(acc, pb0, (1.0f - wzh) * w1y);   // plane1: H = z
    acc_texel(acc, pb1, wzh * w1y);
    acc_texel(acc, pc0, (1.0f - wxh) * w2z);   // plane2: H = x
    acc_texel(acc, pc1, wxh * w2z);

    // half exchange: 4 SHFLs, each lane sends the half it doesn't keep
    unsigned mask = __activemask();
    float res[4];
#pragma unroll
    for (int c = 0; c < 4; c++) {
        float keep = r ? acc[c + 4] : acc[c];
        float send = r ? acc[c]     : acc[c + 4];
        res[c] = keep + __shfl_xor_sync(mask, send, 1);
    }

    reinterpret_cast<float4*>(out)[(size_t)n * 2 + r] =
        make_float4(res[0], res[1], res[2], res[3]);
}

extern "C" void kernel_launch(void* const* d_in, const int* in_sizes, int n_in,
                              void* d_out, int out_size) {
    const float* xyz   = (const float*)d_in[0];
    const int*   bound = (const int*)d_in[1];
    const float* Lg    = (const float*)d_in[2];
    const float* Hp    = (const float*)d_in[3];
    float* out = (float*)d_out;

    int N = in_sizes[0] / 3;
    int M = in_sizes[0];       // total floats in xyz

    bbox_kernel<<<1024, 256>>>(xyz, M);

    transpose_all_kernel<<<2048, 256>>>(Lg, Hp, bound);

    gather_kernel<<<(2 * N + 255) / 256, 256>>>(xyz, bound, out, N);
}